// round 1
// baseline (speedup 1.0000x reference)
#include <cuda_runtime.h>
#include <math.h>

// ---------------------------------------------------------------------------
// Problem constants (fixed by the reference: B=16, H=W=56, DIM=384, HEADS=12, WS=7)
// ---------------------------------------------------------------------------
#define DIMC   384
#define HEADS  12
#define HD     32            // head dim
#define WS     7
#define IMH    56
#define IMW    56
#define BATCH  16
#define NTOK   (IMH * IMW)           // 3136
#define WGRID  8                     // 56/7 windows per side
#define NWIN   (WGRID * WGRID)       // 64
#define WTOK   (WS * WS)             // 49
#define MROWS  (BATCH * NTOK)        // 50176
#define QKVN   (3 * DIMC)            // 1152

// Scratch (device-global: no runtime allocation allowed)
__device__ float g_qkv[(size_t)MROWS * QKVN];   // (B*N, 3C)
__device__ float g_y[(size_t)MROWS * DIMC];     // attn_out + v_lim

// ---------------------------------------------------------------------------
// tf32 helpers
// ---------------------------------------------------------------------------
__device__ __forceinline__ unsigned f2tf32(float x) {
    unsigned r;
    asm("cvt.rna.tf32.f32 %0, %1;" : "=r"(r) : "f"(x));
    return r;
}

__device__ __forceinline__ void mma_tf32(float* d, const unsigned* a, const unsigned* b) {
    asm volatile(
        "mma.sync.aligned.m16n8k8.row.col.f32.tf32.tf32.f32 "
        "{%0,%1,%2,%3}, {%4,%5,%6,%7}, {%8,%9}, {%0,%1,%2,%3};\n"
        : "+f"(d[0]), "+f"(d[1]), "+f"(d[2]), "+f"(d[3])
        : "r"(a[0]), "r"(a[1]), "r"(a[2]), "r"(a[3]), "r"(b[0]), "r"(b[1]));
}

// ---------------------------------------------------------------------------
// tf32 GEMM:  C[M,Nt] = A[M,K] @ B[K,Nt] (+ bias[Nt])
// Tile: 128x128x32, 256 threads (8 warps in 2(M) x 4(N)), warp tile 64x32.
// Requires M%128==0, Nt%128==0 (here 1152/384), K%32==0 (384). All satisfied.
// ---------------------------------------------------------------------------
__global__ __launch_bounds__(256, 2) void gemm_tf32(
    const float* __restrict__ A, const float* __restrict__ Bm,
    const float* __restrict__ bias, float* __restrict__ C,
    int Mtot, int Ntot, int K)
{
    constexpr int BM = 128, BN = 128, BK = 32;
    constexpr int AS_STRIDE = 36;   // 32 + 4 pad (conflict-free fragment reads)
    constexpr int BS_STRIDE = 132;  // 128 + 4 pad

    __shared__ unsigned As[BM * AS_STRIDE];
    __shared__ unsigned Bs[BK * BS_STRIDE];

    const int tid  = threadIdx.x;
    const int wid  = tid >> 5;
    const int lane = tid & 31;
    const int gID  = lane >> 2;     // 0..7
    const int tig  = lane & 3;      // 0..3
    const int wm   = (wid & 1) * 64;   // warp M offset in tile
    const int wn   = (wid >> 1) * 32;  // warp N offset in tile
    const int bm   = blockIdx.y * BM;
    const int bn   = blockIdx.x * BN;

    float acc[4][4][4];
    #pragma unroll
    for (int mt = 0; mt < 4; mt++)
        #pragma unroll
        for (int nt = 0; nt < 4; nt++)
            #pragma unroll
            for (int r = 0; r < 4; r++) acc[mt][nt][r] = 0.0f;

    for (int kb = 0; kb < K; kb += BK) {
        // ---- load A tile (128x32) : convert to tf32 at store time ----
        #pragma unroll
        for (int i = 0; i < 4; i++) {
            int idx = tid + i * 256;
            int m   = idx >> 3;
            int k4  = (idx & 7) * 4;
            float4 v = *(const float4*)(A + (size_t)(bm + m) * K + kb + k4);
            unsigned* dst = &As[m * AS_STRIDE + k4];
            dst[0] = f2tf32(v.x); dst[1] = f2tf32(v.y);
            dst[2] = f2tf32(v.z); dst[3] = f2tf32(v.w);
        }
        // ---- load B tile (32x128) ----
        #pragma unroll
        for (int i = 0; i < 4; i++) {
            int idx = tid + i * 256;
            int k   = idx >> 5;
            int n4  = (idx & 31) * 4;
            float4 v = *(const float4*)(Bm + (size_t)(kb + k) * Ntot + bn + n4);
            unsigned* dst = &Bs[k * BS_STRIDE + n4];
            dst[0] = f2tf32(v.x); dst[1] = f2tf32(v.y);
            dst[2] = f2tf32(v.z); dst[3] = f2tf32(v.w);
        }
        __syncthreads();

        #pragma unroll
        for (int kk = 0; kk < 4; kk++) {           // 4 k-steps of 8
            unsigned afr[4][4];
            unsigned bfr[4][2];
            const int kcol = kk * 8 + tig;
            #pragma unroll
            for (int mt = 0; mt < 4; mt++) {
                int r = wm + mt * 16 + gID;
                afr[mt][0] = As[r * AS_STRIDE + kcol];
                afr[mt][1] = As[(r + 8) * AS_STRIDE + kcol];
                afr[mt][2] = As[r * AS_STRIDE + kcol + 4];
                afr[mt][3] = As[(r + 8) * AS_STRIDE + kcol + 4];
            }
            #pragma unroll
            for (int nt = 0; nt < 4; nt++) {
                int cc = wn + nt * 8 + gID;
                bfr[nt][0] = Bs[kcol * BS_STRIDE + cc];
                bfr[nt][1] = Bs[(kcol + 4) * BS_STRIDE + cc];
            }
            #pragma unroll
            for (int mt = 0; mt < 4; mt++)
                #pragma unroll
                for (int nt = 0; nt < 4; nt++)
                    mma_tf32(acc[mt][nt], afr[mt], bfr[nt]);
        }
        __syncthreads();
    }

    // ---- epilogue ----
    #pragma unroll
    for (int mt = 0; mt < 4; mt++) {
        int r0 = bm + wm + mt * 16 + gID;
        #pragma unroll
        for (int nt = 0; nt < 4; nt++) {
            int c0 = bn + wn + nt * 8 + tig * 2;
            float b0 = bias ? bias[c0]     : 0.0f;
            float b1 = bias ? bias[c0 + 1] : 0.0f;
            C[(size_t)r0 * Ntot + c0]           = acc[mt][nt][0] + b0;
            C[(size_t)r0 * Ntot + c0 + 1]       = acc[mt][nt][1] + b1;
            C[(size_t)(r0 + 8) * Ntot + c0]     = acc[mt][nt][2] + b0;
            C[(size_t)(r0 + 8) * Ntot + c0 + 1] = acc[mt][nt][3] + b1;
        }
    }
}

// ---------------------------------------------------------------------------
// Window attention (fp32). One block per (b, window, head). 128 threads.
// Reads q/k/v slices from g_qkv, writes attention output into g_y.
// ---------------------------------------------------------------------------
__global__ __launch_bounds__(128) void attn_kernel()
{
    const int blk = blockIdx.x;                // b*NWIN*HEADS + w*HEADS + h
    const int h = blk % HEADS;
    const int w = (blk / HEADS) % NWIN;
    const int b = blk / (HEADS * NWIN);
    const int wr = w >> 3;                     // window row (WGRID=8)
    const int wc = w & 7;
    const int tid = threadIdx.x;

    __shared__ float qs[WTOK][HD];
    __shared__ float ks[WTOK][HD];
    __shared__ float vs[WTOK][HD];
    __shared__ float sc[WTOK * WTOK];

    // load q, k, v for this (window, head)
    for (int idx = tid; idx < WTOK * HD; idx += 128) {
        int t = idx >> 5, d = idx & 31;
        int r = t / WS, c = t - r * WS;
        int n = (wr * WS + r) * IMW + wc * WS + c;
        size_t base = (size_t)(b * NTOK + n) * QKVN + h * HD + d;
        qs[t][d] = g_qkv[base];
        ks[t][d] = g_qkv[base + DIMC];
        vs[t][d] = g_qkv[base + 2 * DIMC];
    }
    __syncthreads();

    // scores: 49x49
    const float scale = 0.17677669529663687f;  // 32^-0.5
    for (int idx = tid; idx < WTOK * WTOK; idx += 128) {
        int i = idx / WTOK, j = idx - i * WTOK;
        float s = 0.0f;
        #pragma unroll
        for (int d = 0; d < HD; d++) s += qs[i][d] * ks[j][d];
        sc[idx] = s * scale;
    }
    __syncthreads();

    // softmax per row (max-subtracted, matching jax.nn.softmax)
    if (tid < WTOK) {
        float m = -1e30f;
        #pragma unroll 7
        for (int j = 0; j < WTOK; j++) m = fmaxf(m, sc[tid * WTOK + j]);
        float sum = 0.0f;
        #pragma unroll 7
        for (int j = 0; j < WTOK; j++) {
            float e = __expf(sc[tid * WTOK + j] - m);
            sc[tid * WTOK + j] = e;
            sum += e;
        }
        float inv = 1.0f / sum;
        #pragma unroll 7
        for (int j = 0; j < WTOK; j++) sc[tid * WTOK + j] *= inv;
    }
    __syncthreads();

    // out = P @ V, scatter back to (B,N,C) layout
    for (int idx = tid; idx < WTOK * HD; idx += 128) {
        int i = idx >> 5, d = idx & 31;
        float o = 0.0f;
        #pragma unroll 7
        for (int j = 0; j < WTOK; j++) o += sc[i * WTOK + j] * vs[j][d];
        int r = i / WS, c = i - r * WS;
        int n = (wr * WS + r) * IMW + wc * WS + c;
        g_y[(size_t)(b * NTOK + n) * DIMC + h * HD + d] = o;
    }
}

// ---------------------------------------------------------------------------
// Depthwise 3x3 conv (SAME, zero-pad) on V, accumulated into g_y.
// One block per pixel (b, n), one thread per channel -> coalesced C reads.
// ---------------------------------------------------------------------------
__global__ __launch_bounds__(DIMC) void dwconv_kernel(
    const float* __restrict__ w_conv, const float* __restrict__ b_conv)
{
    const int p = blockIdx.x;          // b*NTOK + n
    const int n = p % NTOK;
    const int b = p / NTOK;
    const int r = n / IMW, c = n - r * IMW;
    const int ch = threadIdx.x;

    float acc = b_conv[ch];
    #pragma unroll
    for (int dy = 0; dy < 3; dy++) {
        int rr = r + dy - 1;
        if (rr < 0 || rr >= IMH) continue;
        #pragma unroll
        for (int dx = 0; dx < 3; dx++) {
            int cc = c + dx - 1;
            if (cc < 0 || cc >= IMW) continue;
            float v = g_qkv[(size_t)(b * NTOK + rr * IMW + cc) * QKVN + 2 * DIMC + ch];
            acc += v * w_conv[(dy * 3 + dx) * DIMC + ch];
        }
    }
    g_y[(size_t)p * DIMC + ch] += acc;
}

// ---------------------------------------------------------------------------
// Launch
// ---------------------------------------------------------------------------
extern "C" void kernel_launch(void* const* d_in, const int* in_sizes, int n_in,
                              void* d_out, int out_size)
{
    const float* x      = (const float*)d_in[0];
    const float* w_qkv  = (const float*)d_in[1];
    const float* w_proj = (const float*)d_in[2];
    const float* b_proj = (const float*)d_in[3];
    const float* w_conv = (const float*)d_in[4];
    const float* b_conv = (const float*)d_in[5];
    float* out = (float*)d_out;

    float* qkv = nullptr;
    float* y   = nullptr;
    cudaGetSymbolAddress((void**)&qkv, g_qkv);
    cudaGetSymbolAddress((void**)&y,   g_y);

    // 1) qkv = x @ w_qkv            (50176 x 1152 x 384)
    {
        dim3 grid(QKVN / 128, MROWS / 128);
        gemm_tf32<<<grid, 256>>>(x, w_qkv, nullptr, qkv, MROWS, QKVN, DIMC);
    }
    // 2) windowed attention -> y
    attn_kernel<<<BATCH * NWIN * HEADS, 128>>>();
    // 3) y += dwconv3x3(v) + b_conv
    dwconv_kernel<<<MROWS, DIMC>>>(w_conv, b_conv);
    // 4) out = y @ w_proj + b_proj  (50176 x 384 x 384)
    {
        dim3 grid(DIMC / 128, MROWS / 128);
        gemm_tf32<<<grid, 256>>>(y, w_proj, b_proj, out, MROWS, DIMC, DIMC);
    }
}

// round 17
// speedup vs baseline: 2.1875x; 2.1875x over previous
#include <cuda_runtime.h>
#include <math.h>

// ---------------------------------------------------------------------------
// Problem constants (B=16, H=W=56, DIM=384, HEADS=12, WS=7)
// ---------------------------------------------------------------------------
#define DIMC   384
#define HEADS  12
#define HD     32
#define WS     7
#define IMH    56
#define IMW    56
#define BATCH  16
#define NTOK   (IMH * IMW)           // 3136
#define WGRID  8
#define NWIN   (WGRID * WGRID)       // 64
#define WTOK   (WS * WS)             // 49
#define MROWS  (BATCH * NTOK)        // 50176
#define QKVN   (3 * DIMC)            // 1152

// Scratch (device-global: no runtime allocation allowed)
__device__ float g_qkv[(size_t)MROWS * QKVN];   // (B*N, 3C)
__device__ float g_y[(size_t)MROWS * DIMC];     // attn_out + v_lim

// ---------------------------------------------------------------------------
// tf32 helpers
// ---------------------------------------------------------------------------
__device__ __forceinline__ unsigned f2tf32(float x) {
    unsigned r;
    asm("cvt.rna.tf32.f32 %0, %1;" : "=r"(r) : "f"(x));
    return r;
}

__device__ __forceinline__ void mma_tf32(float* d, const unsigned* a, const unsigned* b) {
    asm volatile(
        "mma.sync.aligned.m16n8k8.row.col.f32.tf32.tf32.f32 "
        "{%0,%1,%2,%3}, {%4,%5,%6,%7}, {%8,%9}, {%0,%1,%2,%3};\n"
        : "+f"(d[0]), "+f"(d[1]), "+f"(d[2]), "+f"(d[3])
        : "r"(a[0]), "r"(a[1]), "r"(a[2]), "r"(a[3]), "r"(b[0]), "r"(b[1]));
}

// ---------------------------------------------------------------------------
// tf32 GEMM:  C[M,Nt] = A[M,K] @ B[K,Nt] (+ bias[Nt])
// Tile 128x128x32, 256 threads (8 warps, 2Mx4N), warp tile 64x32.
// Conflict-free strides: AS_STRIDE=36 (bank 4*gID+tig perm),
// BS_STRIDE=136 (bank 8*tig+gID perm). Vectorized STS.128 tile fills.
// ---------------------------------------------------------------------------
__global__ __launch_bounds__(256, 2) void gemm_tf32(
    const float* __restrict__ A, const float* __restrict__ Bm,
    const float* __restrict__ bias, float* __restrict__ C,
    int Mtot, int Ntot, int K)
{
    constexpr int BM = 128, BN = 128, BK = 32;
    constexpr int AS_STRIDE = 36;
    constexpr int BS_STRIDE = 136;

    __shared__ unsigned As[BM * AS_STRIDE];
    __shared__ unsigned Bs[BK * BS_STRIDE];

    const int tid  = threadIdx.x;
    const int wid  = tid >> 5;
    const int lane = tid & 31;
    const int gID  = lane >> 2;
    const int tig  = lane & 3;
    const int wm   = (wid & 1) * 64;
    const int wn   = (wid >> 1) * 32;
    const int bm   = blockIdx.y * BM;
    const int bn   = blockIdx.x * BN;

    float acc[4][4][4];
    #pragma unroll
    for (int mt = 0; mt < 4; mt++)
        #pragma unroll
        for (int nt = 0; nt < 4; nt++)
            #pragma unroll
            for (int r = 0; r < 4; r++) acc[mt][nt][r] = 0.0f;

    for (int kb = 0; kb < K; kb += BK) {
        // ---- A tile (128x32): LDG.128 -> cvt.rna.tf32 -> STS.128 ----
        #pragma unroll
        for (int i = 0; i < 4; i++) {
            int idx = tid + i * 256;
            int m   = idx >> 3;
            int k4  = (idx & 7) * 4;
            float4 v = *(const float4*)(A + (size_t)(bm + m) * K + kb + k4);
            uint4 t;
            t.x = f2tf32(v.x); t.y = f2tf32(v.y);
            t.z = f2tf32(v.z); t.w = f2tf32(v.w);
            *(uint4*)&As[m * AS_STRIDE + k4] = t;
        }
        // ---- B tile (32x128) ----
        #pragma unroll
        for (int i = 0; i < 4; i++) {
            int idx = tid + i * 256;
            int k   = idx >> 5;
            int n4  = (idx & 31) * 4;
            float4 v = *(const float4*)(Bm + (size_t)(kb + k) * Ntot + bn + n4);
            uint4 t;
            t.x = f2tf32(v.x); t.y = f2tf32(v.y);
            t.z = f2tf32(v.z); t.w = f2tf32(v.w);
            *(uint4*)&Bs[k * BS_STRIDE + n4] = t;
        }
        __syncthreads();

        #pragma unroll
        for (int kk = 0; kk < 4; kk++) {
            unsigned afr[4][4];
            unsigned bfr[4][2];
            const int kcol = kk * 8 + tig;
            #pragma unroll
            for (int mt = 0; mt < 4; mt++) {
                int r = wm + mt * 16 + gID;
                afr[mt][0] = As[r * AS_STRIDE + kcol];
                afr[mt][1] = As[(r + 8) * AS_STRIDE + kcol];
                afr[mt][2] = As[r * AS_STRIDE + kcol + 4];
                afr[mt][3] = As[(r + 8) * AS_STRIDE + kcol + 4];
            }
            #pragma unroll
            for (int nt = 0; nt < 4; nt++) {
                int cc = wn + nt * 8 + gID;
                bfr[nt][0] = Bs[kcol * BS_STRIDE + cc];
                bfr[nt][1] = Bs[(kcol + 4) * BS_STRIDE + cc];
            }
            #pragma unroll
            for (int mt = 0; mt < 4; mt++)
                #pragma unroll
                for (int nt = 0; nt < 4; nt++)
                    mma_tf32(acc[mt][nt], afr[mt], bfr[nt]);
        }
        __syncthreads();
    }

    #pragma unroll
    for (int mt = 0; mt < 4; mt++) {
        int r0 = bm + wm + mt * 16 + gID;
        #pragma unroll
        for (int nt = 0; nt < 4; nt++) {
            int c0 = bn + wn + nt * 8 + tig * 2;
            float b0 = bias ? bias[c0]     : 0.0f;
            float b1 = bias ? bias[c0 + 1] : 0.0f;
            C[(size_t)r0 * Ntot + c0]           = acc[mt][nt][0] + b0;
            C[(size_t)r0 * Ntot + c0 + 1]       = acc[mt][nt][1] + b1;
            C[(size_t)(r0 + 8) * Ntot + c0]     = acc[mt][nt][2] + b0;
            C[(size_t)(r0 + 8) * Ntot + c0 + 1] = acc[mt][nt][3] + b1;
        }
    }
}

// ---------------------------------------------------------------------------
// Window attention via tf32 MMA.
// One block (128 threads, 4 warps) per (b, window, head).
// M padded 49->64 (4 m16 tiles, one per warp), N(keys) padded 49->56 (7 n8),
// K(dim)=32 (4 k8). Scores -> smem fp32 -> exact softmax -> P as tf32 -> P@V.
// ---------------------------------------------------------------------------
#define QKS 33      // qs/ks/vs row stride (pad to kill bank conflicts)
#define SST 57      // score row stride

__global__ __launch_bounds__(128) void attn_mma()
{
    const int blk = blockIdx.x;
    const int h = blk % HEADS;
    const int w = (blk / HEADS) % NWIN;
    const int b = blk / (HEADS * NWIN);
    const int wr = w >> 3;
    const int wc = w & 7;
    const int tid  = threadIdx.x;
    const int wid  = tid >> 5;
    const int lane = tid & 31;
    const int gID  = lane >> 2;
    const int tig  = lane & 3;

    __shared__ unsigned qs[64 * QKS];   // tf32(Q*scale), rows 49..63 zero
    __shared__ unsigned ks[56 * QKS];   // tf32(K), rows 49..55 zero
    __shared__ unsigned vs[56 * QKS];   // tf32(V), rows 49..55 zero
    __shared__ float    S[64 * SST];    // scores fp32, then P (tf32 bits)

    const float scale = 0.17677669529663687f;  // 32^-0.5

    // ---- load Q,K,V (49 tokens x 32 dims), convert to tf32 ----
    for (int idx = tid; idx < WTOK * HD; idx += 128) {
        int t = idx >> 5, d = idx & 31;
        int r = t / WS, c = t - r * WS;
        int n = (wr * WS + r) * IMW + wc * WS + c;
        size_t base = (size_t)(b * NTOK + n) * QKVN + h * HD + d;
        qs[t * QKS + d] = f2tf32(g_qkv[base] * scale);
        ks[t * QKS + d] = f2tf32(g_qkv[base + DIMC]);
        vs[t * QKS + d] = f2tf32(g_qkv[base + 2 * DIMC]);
    }
    // zero pad rows
    for (int idx = WTOK * HD + tid; idx < 64 * HD; idx += 128) {
        int t = idx >> 5, d = idx & 31;
        qs[t * QKS + d] = 0u;
        if (t < 56) { ks[t * QKS + d] = 0u; vs[t * QKS + d] = 0u; }
    }
    __syncthreads();

    // ---- scores: S[i][j] = (Q*scale)[i,:] . K[j,:]  (warp wid owns m-tile wid)
    {
        const int mrow = wid * 16 + gID;
        unsigned afr[4][4];
        #pragma unroll
        for (int kk = 0; kk < 4; kk++) {
            int kc = kk * 8 + tig;
            afr[kk][0] = qs[mrow * QKS + kc];
            afr[kk][1] = qs[(mrow + 8) * QKS + kc];
            afr[kk][2] = qs[mrow * QKS + kc + 4];
            afr[kk][3] = qs[(mrow + 8) * QKS + kc + 4];
        }
        #pragma unroll
        for (int nt = 0; nt < 7; nt++) {
            float acc[4] = {0.f, 0.f, 0.f, 0.f};
            int j = nt * 8 + gID;
            #pragma unroll
            for (int kk = 0; kk < 4; kk++) {
                unsigned bfr[2];
                int kc = kk * 8 + tig;
                bfr[0] = ks[j * QKS + kc];
                bfr[1] = ks[j * QKS + kc + 4];
                mma_tf32(acc, afr[kk], bfr);
            }
            int c0 = nt * 8 + tig * 2;
            S[mrow * SST + c0]           = acc[0];
            S[mrow * SST + c0 + 1]       = acc[1];
            S[(mrow + 8) * SST + c0]     = acc[2];
            S[(mrow + 8) * SST + c0 + 1] = acc[3];
        }
    }
    __syncthreads();

    // ---- softmax rows 0..48 over cols 0..48; write P as tf32; zero pad cols
    if (tid < WTOK) {
        float* row = &S[tid * SST];
        float m = -1e30f;
        #pragma unroll 7
        for (int j = 0; j < WTOK; j++) m = fmaxf(m, row[j]);
        float sum = 0.0f;
        float e[WTOK];
        #pragma unroll 7
        for (int j = 0; j < WTOK; j++) { e[j] = __expf(row[j] - m); sum += e[j]; }
        float inv = 1.0f / sum;
        #pragma unroll 7
        for (int j = 0; j < WTOK; j++) row[j] = __uint_as_float(f2tf32(e[j] * inv));
        #pragma unroll
        for (int j = WTOK; j < 56; j++) row[j] = 0.0f;
    }
    __syncthreads();
    // P rows 49..63 hold scores computed from zero Q rows => exactly 0.0,
    // valid tf32; padded V rows are zero, so no masking needed.

    // ---- out = P @ V  (K-dim = keys, 7 k8 steps; N-dim = 32 dims, 4 n8)
    {
        const int mrow = wid * 16 + gID;
        const unsigned* Su = (const unsigned*)S;
        unsigned afr[7][4];
        #pragma unroll
        for (int kk = 0; kk < 7; kk++) {
            int kc = kk * 8 + tig;
            afr[kk][0] = Su[mrow * SST + kc];
            afr[kk][1] = Su[(mrow + 8) * SST + kc];
            afr[kk][2] = Su[mrow * SST + kc + 4];
            afr[kk][3] = Su[(mrow + 8) * SST + kc + 4];
        }
        #pragma unroll
        for (int nt = 0; nt < 4; nt++) {
            float acc[4] = {0.f, 0.f, 0.f, 0.f};
            #pragma unroll
            for (int kk = 0; kk < 7; kk++) {
                unsigned bfr[2];
                int kr = kk * 8 + tig;
                bfr[0] = vs[kr * QKS + nt * 8 + gID];
                bfr[1] = vs[(kr + 4) * QKS + nt * 8 + gID];
                mma_tf32(acc, afr[kk], bfr);
            }
            // scatter to g_y (only valid rows < 49)
            int c0 = h * HD + nt * 8 + tig * 2;
            #pragma unroll
            for (int half = 0; half < 2; half++) {
                int i = mrow + half * 8;
                if (i < WTOK) {
                    int r = i / WS, c = i - r * WS;
                    int n = (wr * WS + r) * IMW + wc * WS + c;
                    float* dst = &g_y[(size_t)(b * NTOK + n) * DIMC + c0];
                    dst[0] = acc[half * 2];
                    dst[1] = acc[half * 2 + 1];
                }
            }
        }
    }
}

// ---------------------------------------------------------------------------
// Depthwise 3x3 conv (SAME) on V, accumulated into g_y. float4, 4 pixels/block.
// 384 threads: thread handles pixel (blk*4 + t/96), channels (t%96)*4 .. +3.
// ---------------------------------------------------------------------------
__global__ __launch_bounds__(384) void dwconv_kernel(
    const float* __restrict__ w_conv, const float* __restrict__ b_conv)
{
    const int t  = threadIdx.x;
    const int p  = blockIdx.x * 4 + (t / 96);   // b*NTOK + n
    const int cq = (t % 96) * 4;
    const int n = p % NTOK;
    const int b = p / NTOK;
    const int r = n / IMW, c = n - r * IMW;

    float4 bias = *(const float4*)(b_conv + cq);
    float ax = bias.x, ay = bias.y, az = bias.z, aw = bias.w;

    #pragma unroll
    for (int dy = 0; dy < 3; dy++) {
        int rr = r + dy - 1;
        if (rr < 0 || rr >= IMH) continue;
        #pragma unroll
        for (int dx = 0; dx < 3; dx++) {
            int cc = c + dx - 1;
            if (cc < 0 || cc >= IMW) continue;
            float4 v = *(const float4*)(g_qkv + (size_t)(b * NTOK + rr * IMW + cc) * QKVN + 2 * DIMC + cq);
            float4 wv = *(const float4*)(w_conv + (dy * 3 + dx) * DIMC + cq);
            ax += v.x * wv.x; ay += v.y * wv.y;
            az += v.z * wv.z; aw += v.w * wv.w;
        }
    }
    float4* yp = (float4*)(g_y + (size_t)p * DIMC + cq);
    float4 old = *yp;
    old.x += ax; old.y += ay; old.z += az; old.w += aw;
    *yp = old;
}

// ---------------------------------------------------------------------------
// Launch
// ---------------------------------------------------------------------------
extern "C" void kernel_launch(void* const* d_in, const int* in_sizes, int n_in,
                              void* d_out, int out_size)
{
    const float* x      = (const float*)d_in[0];
    const float* w_qkv  = (const float*)d_in[1];
    const float* w_proj = (const float*)d_in[2];
    const float* b_proj = (const float*)d_in[3];
    const float* w_conv = (const float*)d_in[4];
    const float* b_conv = (const float*)d_in[5];
    float* out = (float*)d_out;

    float* qkv = nullptr;
    float* y   = nullptr;
    cudaGetSymbolAddress((void**)&qkv, g_qkv);
    cudaGetSymbolAddress((void**)&y,   g_y);

    // 1) qkv = x @ w_qkv            (50176 x 1152 x 384)
    {
        dim3 grid(QKVN / 128, MROWS / 128);
        gemm_tf32<<<grid, 256>>>(x, w_qkv, nullptr, qkv, MROWS, QKVN, DIMC);
    }
    // 2) windowed attention (tf32 mma) -> y
    attn_mma<<<BATCH * NWIN * HEADS, 128>>>();
    // 3) y += dwconv3x3(v) + b_conv
    dwconv_kernel<<<MROWS / 4, 384>>>(w_conv, b_conv);
    // 4) out = y @ w_proj + b_proj  (50176 x 384 x 384)
    {
        dim3 grid(DIMC / 128, MROWS / 128);
        gemm_tf32<<<grid, 256>>>(y, w_proj, b_proj, out, MROWS, DIMC, DIMC);
    }
}